// round 14
// baseline (speedup 1.0000x reference)
#include <cuda_runtime.h>
#include <cstdint>
#include <cmath>

// ---------------------------------------------------------------------------
// L1Wav prox (R11 = R10 + shuffle-based horizontal analysis):
//  - k_fwd1: one aligned LDG.128 per thread + warp shuffles build the 8-tap
//    window (L1 wavefronts/warp ~9 vs ~36). Exact grids -> full warps always.
//  - k_inv1: (e,o) merged into one STG.128 (stride-1 float4 stores).
//  - vertical kernels keep R10 chunk-8 sliding windows.
// Output real-only float32; roll fused fwd-L0, un-roll fused inv-L0.
// ---------------------------------------------------------------------------

#define STR 4096u
#define NTOP 4096u
#define THRESH 0.005f

#define DECL_FILTERS \
    const float LO[8] = { \
        -0.010597401784997278f,  0.032883011666982945f,  0.030841381835986965f, \
        -0.18703481171888114f,  -0.02798376941698385f,   0.6308807679295904f, \
         0.7148465705525415f,    0.23037781330885523f }; \
    const float HI[8] = { \
         0.23037781330885523f,  -0.7148465705525415f,    0.6308807679295904f, \
         0.02798376941698385f,  -0.18703481171888114f,  -0.030841381835986965f, \
         0.032883011666982945f,  0.010597401784997278f };

__device__ __align__(16) float2 g_A[STR * STR];
__device__ __align__(16) float2 g_B[STR * STR];

__device__ __forceinline__ void fma2(float2& a, float c, float2 v) {
    a.x = fmaf(c, v.x, a.x);
    a.y = fmaf(c, v.y, a.y);
}

__device__ __forceinline__ float2 softt(float2 v) {
    float m2 = v.x * v.x + v.y * v.y;
    if (m2 <= THRESH * THRESH) return make_float2(0.f, 0.f);
    float s = 1.0f - THRESH * rsqrtf(m2);
    return make_float2(v.x * s, v.y * s);
}

__device__ __forceinline__ float4 shfl4(float4 v, unsigned src) {
    float4 r;
    r.x = __shfl_sync(0xffffffffu, v.x, src);
    r.y = __shfl_sync(0xffffffffu, v.y, src);
    r.z = __shfl_sync(0xffffffffu, v.z, src);
    r.w = __shfl_sync(0xffffffffu, v.w, src);
    return r;
}

// ---- forward axis0 level 0, fused roll, chunk=8 (R10) ----
__global__ __launch_bounds__(256)
void k_fwd0_roll(const float* __restrict__ xr, const float* __restrict__ xi,
                 int sh) {
    DECL_FILTERS
    unsigned j = blockIdx.x * 256u + threadIdx.x;
    unsigned n0 = blockIdx.y * 8u;
    unsigned jc = (j - (unsigned)sh) & (NTOP - 1u);
    float2 w[8];
#pragma unroll
    for (unsigned k = 0; k < 8u; k++) {
        unsigned r = (2u * n0 + k - (unsigned)sh) & (NTOP - 1u);
        w[k] = make_float2(xr[r * STR + jc], xi[r * STR + jc]);
    }
#pragma unroll
    for (unsigned m = 0; m < 8u; m++) {
        unsigned n = n0 + m;
        float2 a = {0, 0}, d = {0, 0};
#pragma unroll
        for (int k = 0; k < 8; k++) {
            fma2(a, LO[k], w[k]);
            fma2(d, HI[k], w[k]);
        }
        g_B[n * STR + j] = a;
        g_B[(n + (NTOP >> 1)) * STR + j] = d;
        if (m < 7u) {
#pragma unroll
            for (int k = 0; k < 6; k++) w[k] = w[k + 2];
            unsigned r0 = (2u * n + 8u - (unsigned)sh) & (NTOP - 1u);
            unsigned r1 = (2u * n + 9u - (unsigned)sh) & (NTOP - 1u);
            w[6] = make_float2(xr[r0 * STR + jc], xi[r0 * STR + jc]);
            w[7] = make_float2(xr[r1 * STR + jc], xi[r1 * STR + jc]);
        }
    }
}

// ---- forward axis0 generic: A -> B, chunked (R10) ----
__global__ __launch_bounds__(256)
void k_fwd0(unsigned N, unsigned chunk) {
    DECL_FILTERS
    unsigned j = blockIdx.x * 256u + threadIdx.x;
    if (j >= N) return;
    unsigned n0 = blockIdx.y * chunk;
    unsigned h = N >> 1;
    float2 w[8];
#pragma unroll
    for (unsigned k = 0; k < 8u; k++)
        w[k] = g_A[((2u * n0 + k) & (N - 1u)) * STR + j];
    for (unsigned m = 0; m < chunk; m++) {
        unsigned n = n0 + m;
        float2 a = {0, 0}, d = {0, 0};
#pragma unroll
        for (int k = 0; k < 8; k++) {
            fma2(a, LO[k], w[k]);
            fma2(d, HI[k], w[k]);
        }
        g_B[n * STR + j] = a;
        g_B[(n + h) * STR + j] = d;
        if (m + 1u < chunk) {
#pragma unroll
            for (int k = 0; k < 6; k++) w[k] = w[k + 2];
            w[6] = g_A[((2u * n + 8u) & (N - 1u)) * STR + j];
            w[7] = g_A[((2u * n + 9u) & (N - 1u)) * STR + j];
        }
    }
}

// ---- forward axis1 + threshold: B -> A, SHUFFLE version ----
// Window x[2n..2n+7] = float4 f4[n..n+3]; thread loads f4[n], shuffles rest.
// Grids are exact (h multiple of 256) -> all warps full.
__global__ __launch_bounds__(256)
void k_fwd1(unsigned N, int mode) {
    DECL_FILTERS
    unsigned h = N >> 1;
    unsigned lane = threadIdx.x & 31u;
    unsigned n = blockIdx.x * 256u + threadIdx.x;    // < h by exact grid
    unsigned i = blockIdx.y;
    const float4* r4 = reinterpret_cast<const float4*>(g_B + i * STR);
    float4 F = r4[n];
    float4 G = make_float4(0.f, 0.f, 0.f, 0.f);
    if (lane < 3u) G = r4[(n + 32u) & (h - 1u)];
    float4 W1, W2, W3;
    {
        unsigned s1 = (lane + 1u) & 31u;
        float4 tF = shfl4(F, s1), tG = shfl4(G, s1);
        W1 = (lane + 1u >= 32u) ? tG : tF;
        unsigned s2 = (lane + 2u) & 31u;
        tF = shfl4(F, s2); tG = shfl4(G, s2);
        W2 = (lane + 2u >= 32u) ? tG : tF;
        unsigned s3 = (lane + 3u) & 31u;
        tF = shfl4(F, s3); tG = shfl4(G, s3);
        W3 = (lane + 3u >= 32u) ? tG : tF;
    }
    float2 a = {0, 0}, d = {0, 0};
    // W[q].xy = x[2n+2q], W[q].zw = x[2n+2q+1]
    a.x = fmaf(LO[0], F.x, a.x);  a.y = fmaf(LO[0], F.y, a.y);
    a.x = fmaf(LO[1], F.z, a.x);  a.y = fmaf(LO[1], F.w, a.y);
    d.x = fmaf(HI[0], F.x, d.x);  d.y = fmaf(HI[0], F.y, d.y);
    d.x = fmaf(HI[1], F.z, d.x);  d.y = fmaf(HI[1], F.w, d.y);
    a.x = fmaf(LO[2], W1.x, a.x); a.y = fmaf(LO[2], W1.y, a.y);
    a.x = fmaf(LO[3], W1.z, a.x); a.y = fmaf(LO[3], W1.w, a.y);
    d.x = fmaf(HI[2], W1.x, d.x); d.y = fmaf(HI[2], W1.y, d.y);
    d.x = fmaf(HI[3], W1.z, d.x); d.y = fmaf(HI[3], W1.w, d.y);
    a.x = fmaf(LO[4], W2.x, a.x); a.y = fmaf(LO[4], W2.y, a.y);
    a.x = fmaf(LO[5], W2.z, a.x); a.y = fmaf(LO[5], W2.w, a.y);
    d.x = fmaf(HI[4], W2.x, d.x); d.y = fmaf(HI[4], W2.y, d.y);
    d.x = fmaf(HI[5], W2.z, d.x); d.y = fmaf(HI[5], W2.w, d.y);
    a.x = fmaf(LO[6], W3.x, a.x); a.y = fmaf(LO[6], W3.y, a.y);
    a.x = fmaf(LO[7], W3.z, a.x); a.y = fmaf(LO[7], W3.w, a.y);
    d.x = fmaf(HI[6], W3.x, d.x); d.y = fmaf(HI[6], W3.y, d.y);
    d.x = fmaf(HI[7], W3.z, d.x); d.y = fmaf(HI[7], W3.w, d.y);

    bool ta = (mode == 2) || (i >= h);
    g_A[i * STR + n] = ta ? softt(a) : a;
    g_A[i * STR + h + n] = softt(d);
}

// ---- inverse axis1: A quadrants -> stacked a/d in B; STG.128 (e,o) ----
__global__ __launch_bounds__(256)
void k_inv1(unsigned N) {
    DECL_FILTERS
    unsigned p = blockIdx.x * 256u + threadIdx.x;
    unsigned i = blockIdx.y;
    unsigned h = N >> 1;
    if (p >= h) return;
    float2 e = {0, 0}, o = {0, 0};
#pragma unroll
    for (unsigned q = 0; q < 4u; q++) {
        unsigned pp = (p - q + h) & (h - 1u);
        float2 s = g_A[i * STR + pp];
        float2 t = g_A[i * STR + h + pp];
        fma2(e, LO[2 * q], s);     fma2(e, HI[2 * q], t);
        fma2(o, LO[2 * q + 1], s); fma2(o, HI[2 * q + 1], t);
    }
    reinterpret_cast<float4*>(g_B + i * STR)[p] = make_float4(e.x, e.y, o.x, o.y);
}

// ---- inverse axis0: B stacked -> A region, chunked (R10) ----
__global__ __launch_bounds__(256)
void k_inv0(unsigned N, unsigned chunk) {
    DECL_FILTERS
    unsigned j = blockIdx.x * 256u + threadIdx.x;
    if (j >= N) return;
    unsigned p0 = blockIdx.y * chunk;
    unsigned h = N >> 1;
    float2 wa[4], wd[4];
#pragma unroll
    for (unsigned i = 0; i < 4u; i++) {
        unsigned pp = (p0 + i - 3u + h) & (h - 1u);
        wa[i] = g_B[pp * STR + j];
        wd[i] = g_B[(h + pp) * STR + j];
    }
    for (unsigned m = 0; m < chunk; m++) {
        unsigned p = p0 + m;
        float2 e = {0, 0}, o = {0, 0};
#pragma unroll
        for (int q = 0; q < 4; q++) {
            float2 s = wa[3 - q], t = wd[3 - q];
            fma2(e, LO[2 * q], s);     fma2(e, HI[2 * q], t);
            fma2(o, LO[2 * q + 1], s); fma2(o, HI[2 * q + 1], t);
        }
        g_A[(2u * p) * STR + j]      = e;
        g_A[(2u * p + 1u) * STR + j] = o;
        if (m + 1u < chunk) {
#pragma unroll
            for (int i = 0; i < 3; i++) { wa[i] = wa[i + 1]; wd[i] = wd[i + 1]; }
            unsigned pp = (p + 1u) & (h - 1u);
            wa[3] = g_B[pp * STR + j];
            wd[3] = g_B[(h + pp) * STR + j];
        }
    }
}

// ---- final inverse axis0 + un-roll, REAL-only output, chunked (R10) ----
__global__ __launch_bounds__(256)
void k_inv0_out_r(float* __restrict__ out, int sh) {
    DECL_FILTERS
    unsigned j = blockIdx.x * 256u + threadIdx.x;
    unsigned p0 = blockIdx.y * 8u;
    const unsigned h = NTOP >> 1;
    unsigned jc = (j - (unsigned)sh) & (NTOP - 1u);
    float2 wa[4], wd[4];
#pragma unroll
    for (unsigned i = 0; i < 4u; i++) {
        unsigned pp = (p0 + i - 3u + h) & (h - 1u);
        wa[i] = g_B[pp * STR + j];
        wd[i] = g_B[(h + pp) * STR + j];
    }
#pragma unroll
    for (unsigned m = 0; m < 8u; m++) {
        unsigned p = p0 + m;
        float e = 0.f, o = 0.f;
#pragma unroll
        for (int q = 0; q < 4; q++) {
            float sx = wa[3 - q].x, tx = wd[3 - q].x;
            e = fmaf(LO[2 * q], sx, e);     e = fmaf(HI[2 * q], tx, e);
            o = fmaf(LO[2 * q + 1], sx, o); o = fmaf(HI[2 * q + 1], tx, o);
        }
        unsigned r0 = (2u * p - (unsigned)sh) & (NTOP - 1u);
        unsigned r1 = (2u * p + 1u - (unsigned)sh) & (NTOP - 1u);
        out[r0 * NTOP + jc] = e;
        out[r1 * NTOP + jc] = o;
        if (m < 7u) {
#pragma unroll
            for (int i = 0; i < 3; i++) { wa[i] = wa[i + 1]; wd[i] = wd[i + 1]; }
            unsigned pp = (p + 1u) & (h - 1u);
            wa[3] = g_B[pp * STR + j];
            wd[3] = g_B[(h + pp) * STR + j];
        }
    }
}

// ---- defensive complex-output variant ----
__global__ __launch_bounds__(256)
void k_inv0_out_c(float2* __restrict__ out, int sh) {
    DECL_FILTERS
    unsigned j = blockIdx.x * 256u + threadIdx.x;
    unsigned p0 = blockIdx.y * 8u;
    const unsigned h = NTOP >> 1;
    unsigned jc = (j - (unsigned)sh) & (NTOP - 1u);
    float2 wa[4], wd[4];
#pragma unroll
    for (unsigned i = 0; i < 4u; i++) {
        unsigned pp = (p0 + i - 3u + h) & (h - 1u);
        wa[i] = g_B[pp * STR + j];
        wd[i] = g_B[(h + pp) * STR + j];
    }
#pragma unroll
    for (unsigned m = 0; m < 8u; m++) {
        unsigned p = p0 + m;
        float2 e = {0, 0}, o = {0, 0};
#pragma unroll
        for (int q = 0; q < 4; q++) {
            float2 s = wa[3 - q], t = wd[3 - q];
            fma2(e, LO[2 * q], s);     fma2(e, HI[2 * q], t);
            fma2(o, LO[2 * q + 1], s); fma2(o, HI[2 * q + 1], t);
        }
        unsigned r0 = (2u * p - (unsigned)sh) & (NTOP - 1u);
        unsigned r1 = (2u * p + 1u - (unsigned)sh) & (NTOP - 1u);
        out[r0 * NTOP + jc] = e;
        out[r1 * NTOP + jc] = o;
        if (m < 7u) {
#pragma unroll
            for (int i = 0; i < 3; i++) { wa[i] = wa[i + 1]; wd[i] = wd[i + 1]; }
            unsigned pp = (p + 1u) & (h - 1u);
            wa[3] = g_B[pp * STR + j];
            wd[3] = g_B[(h + pp) * STR + j];
        }
    }
}

// ---------------------------------------------------------------------------
// Host: replicate numpy default_rng(1000).uniform(-3,3) -> SHIFT
// ---------------------------------------------------------------------------
static int compute_shift() {
    const uint32_t MULT_A = 0x931e8875u, INIT_A = 0x43b0d7e5u;
    const uint32_t MULT_B = 0x58f38dedu, INIT_B = 0x8b51f9ddu;
    const uint32_t MIX_L = 0xca01f9ddu, MIX_R = 0x4973f715u;

    uint32_t hc = INIT_A;
    auto hashmix = [&](uint32_t v) -> uint32_t {
        v ^= hc; hc *= MULT_A; v *= hc; v ^= v >> 16; return v;
    };
    auto mix = [&](uint32_t x, uint32_t y) -> uint32_t {
        uint32_t r = (x * MIX_L) ^ (y * MIX_R); r ^= r >> 16; return r;
    };

    uint32_t pool[4];
    for (int i = 0; i < 4; i++) pool[i] = hashmix(i < 1 ? 1000u : 0u);
    for (int s = 0; s < 4; s++)
        for (int d = 0; d < 4; d++)
            if (s != d) pool[d] = mix(pool[d], hashmix(pool[s]));

    uint32_t st[8];
    uint32_t hb = INIT_B;
    for (int i = 0; i < 8; i++) {
        uint32_t v = pool[i & 3];
        v ^= hb; hb *= MULT_B; v *= hb; v ^= v >> 16;
        st[i] = v;
    }
    uint64_t w[4];
    for (int i = 0; i < 4; i++)
        w[i] = (uint64_t)st[2 * i] | ((uint64_t)st[2 * i + 1] << 32);

    typedef unsigned __int128 u128;
    const u128 MULT = ((u128)2549297995355413924ULL << 64) | 4865540595714422341ULL;
    u128 initstate = ((u128)w[0] << 64) | w[1];
    u128 initseq   = ((u128)w[2] << 64) | w[3];
    u128 state = 0;
    u128 inc = (initseq << 1) | 1;
    state = state * MULT + inc;
    state += initstate;
    state = state * MULT + inc;
    state = state * MULT + inc;      // first next_uint64
    uint64_t xo = (uint64_t)(state >> 64) ^ (uint64_t)state;
    unsigned rot = (unsigned)(state >> 122);
    uint64_t out64 = (xo >> rot) | (xo << ((64u - rot) & 63u));
    double dd = (double)(out64 >> 11) * (1.0 / 9007199254740992.0);
    double u = -3.0 + 6.0 * dd;
    return (int)nearbyint(u);
}

extern "C" void kernel_launch(void* const* d_in, const int* in_sizes, int n_in,
                              void* d_out, int out_size) {
    const float* xr = (const float*)d_in[0];
    const float* xi = (n_in >= 2) ? (const float*)d_in[1] : (const float*)d_in[0];
    const int sh = compute_shift();

    dim3 blk(256);

    // ---- forward ----
    k_fwd0_roll<<<dim3(16, 256), blk>>>(xr, xi, sh);
    k_fwd1<<<dim3(8, 4096), blk>>>(4096u, 1);
    k_fwd0<<<dim3(8, 128), blk>>>(2048u, 8u);
    k_fwd1<<<dim3(4, 2048), blk>>>(2048u, 1);
    k_fwd0<<<dim3(4, 64), blk>>>(1024u, 8u);
    k_fwd1<<<dim3(2, 1024), blk>>>(1024u, 1);
    k_fwd0<<<dim3(2, 256), blk>>>(512u, 1u);
    k_fwd1<<<dim3(1, 512), blk>>>(512u, 2);   // + LL threshold

    // ---- inverse ----
    k_inv1<<<dim3(1, 512), blk>>>(512u);
    k_inv0<<<dim3(2, 256), blk>>>(512u, 1u);
    k_inv1<<<dim3(2, 1024), blk>>>(1024u);
    k_inv0<<<dim3(4, 64), blk>>>(1024u, 8u);
    k_inv1<<<dim3(4, 2048), blk>>>(2048u);
    k_inv0<<<dim3(8, 128), blk>>>(2048u, 8u);
    k_inv1<<<dim3(8, 4096), blk>>>(4096u);

    if (out_size >= 2 * 16777216) {
        k_inv0_out_c<<<dim3(16, 256), blk>>>((float2*)d_out, sh);
    } else {
        k_inv0_out_r<<<dim3(16, 256), blk>>>((float*)d_out, sh);
    }
}